// round 1
// baseline (speedup 1.0000x reference)
#include <cuda_runtime.h>
#include <math_constants.h>

// Problem constants (match reference setup_inputs)
#define NUM_STATES 10000
#define BATCH      64
#define SEQLEN     4096
#define CHUNKS     16
#define TPB        256   // CHUNKS * TPB = 4096 >= SEQLEN-1 transitions

// Scratch: per-(sequence, chunk) partial sums. __device__ global per harness rules.
__device__ float g_partials[BATCH * CHUNKS];

__global__ __launch_bounds__(TPB)
void trans_partial_kernel(const int* __restrict__ seqs,
                          const int* __restrict__ lengths,
                          const float* __restrict__ trans)
{
    const int b     = blockIdx.y;
    const int chunk = blockIdx.x;
    const int tid   = threadIdx.x;

    // transition target index t in [1, SEQLEN-1]; valid iff t < lengths[b]
    const int t   = chunk * TPB + tid + 1;
    const int len = lengths[b];

    float v = 0.0f;
    if (t < SEQLEN && t < len) {
        const int sp = seqs[b * SEQLEN + t - 1];
        const int sc = seqs[b * SEQLEN + t];
        // random gather into 400MB table: the hot load
        const float p = __ldg(&trans[(size_t)sp * NUM_STATES + sc]);
        v = logf(p);
    }

    // block reduction: warp shuffle + shared
    #pragma unroll
    for (int off = 16; off > 0; off >>= 1)
        v += __shfl_down_sync(0xffffffff, v, off);

    __shared__ float warp_sums[TPB / 32];
    const int lane = tid & 31;
    const int wid  = tid >> 5;
    if (lane == 0) warp_sums[wid] = v;
    __syncthreads();

    if (wid == 0) {
        v = (lane < TPB / 32) ? warp_sums[lane] : 0.0f;
        #pragma unroll
        for (int off = 4; off > 0; off >>= 1)
            v += __shfl_down_sync(0xffffffff, v, off);
        if (lane == 0)
            g_partials[b * CHUNKS + chunk] = v;
    }
}

__global__ __launch_bounds__(BATCH)
void finalize_kernel(const int* __restrict__ seqs,
                     const int* __restrict__ lengths,
                     const float* __restrict__ initial,
                     float* __restrict__ out)
{
    const int b = threadIdx.x;  // 64 threads, one per sequence

    float ll = logf(initial[seqs[b * SEQLEN]]);
    #pragma unroll
    for (int c = 0; c < CHUNKS; c++)
        ll += g_partials[b * CHUNKS + c];

    __shared__ float sll[BATCH];
    sll[b] = ll;
    __syncthreads();

    if (b == 0) {
        float m = -CUDART_INF_F;
        #pragma unroll 8
        for (int i = 0; i < BATCH; i++)
            m = fmaxf(m, sll[i]);
        float s = 0.0f;
        #pragma unroll 8
        for (int i = 0; i < BATCH; i++)
            s += expf(sll[i] - m);
        out[0] = -(m + logf(s));
    }
}

extern "C" void kernel_launch(void* const* d_in, const int* in_sizes, int n_in,
                              void* d_out, int out_size)
{
    const int*   seqs    = (const int*)d_in[0];
    const int*   lengths = (const int*)d_in[1];
    const float* initial = (const float*)d_in[2];
    const float* trans   = (const float*)d_in[3];
    float*       out     = (float*)d_out;

    dim3 grid(CHUNKS, BATCH);
    trans_partial_kernel<<<grid, TPB>>>(seqs, lengths, trans);
    finalize_kernel<<<1, BATCH>>>(seqs, lengths, initial, out);
}

// round 2
// speedup vs baseline: 1.0226x; 1.0226x over previous
#include <cuda_runtime.h>
#include <math_constants.h>

// Problem constants (match reference setup_inputs)
#define NUM_STATES 10000
#define BATCH      64
#define SEQLEN     4096
#define TPB        256
#define TPT        4                          // transitions per thread
#define BLOCKS_PER_SEQ (SEQLEN / (TPB * TPT)) // 4
#define GRID       (BATCH * BLOCKS_PER_SEQ)   // 256

// Scratch (device globals per harness rules)
__device__ float        g_partials[GRID];
__device__ unsigned int g_counter = 0;

__global__ __launch_bounds__(TPB)
void markov_fused_kernel(const int*   __restrict__ seqs,
                         const int*   __restrict__ lengths,
                         const float* __restrict__ initial,
                         const float* __restrict__ trans,
                         float*       __restrict__ out)
{
    const int b    = blockIdx.x >> 2;        // sequence id (4 blocks per sequence)
    const int blk  = blockIdx.x & 3;
    const int tid  = threadIdx.x;
    const int k    = blk * TPB + tid;        // 0..1023 within sequence
    const int base = 4 * k;                  // aligned prev-state base index
    const int len  = lengths[b];
    const int* s   = seqs + b * SEQLEN;

    // prev states [base .. base+3] (16B aligned), plus the following state
    const int4 prev = *reinterpret_cast<const int4*>(s + base);
    const int  nxt  = (base + 4 < SEQLEN) ? s[base + 4] : 0;
    const int  p[5] = {prev.x, prev.y, prev.z, prev.w, nxt};

    // transitions end at t = base+1 .. base+4; valid iff t < len (len <= SEQLEN)
    float v = 0.0f;
    #pragma unroll
    for (int j = 0; j < TPT; j++) {
        const int t = base + 1 + j;
        if (t < SEQLEN && t < len) {
            const float pr = __ldg(&trans[(size_t)p[j] * NUM_STATES + p[j + 1]]);
            v += __logf(pr);
        }
    }

    // ---- block reduction (warp shuffle + shared) ----
    #pragma unroll
    for (int off = 16; off > 0; off >>= 1)
        v += __shfl_down_sync(0xffffffff, v, off);

    __shared__ float warp_sums[TPB / 32];
    const int lane = tid & 31;
    const int wid  = tid >> 5;
    if (lane == 0) warp_sums[wid] = v;
    __syncthreads();

    if (wid == 0) {
        v = (lane < TPB / 32) ? warp_sums[lane] : 0.0f;
        #pragma unroll
        for (int off = 4; off > 0; off >>= 1)
            v += __shfl_down_sync(0xffffffff, v, off);
        if (lane == 0)
            g_partials[blockIdx.x] = v;   // seq b's partials live at [4b .. 4b+3]
    }

    // ---- last-block-done finalize (single launch, deterministic) ----
    __shared__ bool isLast;
    if (tid == 0) {
        __threadfence();
        const unsigned int done = atomicAdd(&g_counter, 1u);
        isLast = (done == GRID - 1);
    }
    __syncthreads();
    if (!isLast) return;

    float ll = 0.0f;
    if (tid < BATCH) {
        ll = __logf(__ldg(&initial[__ldg(&seqs[tid * SEQLEN])]));
        #pragma unroll
        for (int c = 0; c < BLOCKS_PER_SEQ; c++)
            ll += g_partials[tid * BLOCKS_PER_SEQ + c];
    }

    __shared__ float sll[BATCH];
    if (tid < BATCH) sll[tid] = ll;
    __syncthreads();

    if (tid == 0) {
        float m = -CUDART_INF_F;
        #pragma unroll 8
        for (int i = 0; i < BATCH; i++)
            m = fmaxf(m, sll[i]);
        float ssum = 0.0f;
        #pragma unroll 8
        for (int i = 0; i < BATCH; i++)
            ssum += __expf(sll[i] - m);
        out[0] = -(m + __logf(ssum));
        g_counter = 0;   // reset for next graph replay (determinism)
    }
}

extern "C" void kernel_launch(void* const* d_in, const int* in_sizes, int n_in,
                              void* d_out, int out_size)
{
    const int*   seqs    = (const int*)d_in[0];
    const int*   lengths = (const int*)d_in[1];
    const float* initial = (const float*)d_in[2];
    const float* trans   = (const float*)d_in[3];
    float*       out     = (float*)d_out;

    markov_fused_kernel<<<GRID, TPB>>>(seqs, lengths, initial, trans, out);
}

// round 3
// speedup vs baseline: 1.0329x; 1.0101x over previous
#include <cuda_runtime.h>
#include <math_constants.h>

// Problem constants (match reference setup_inputs)
#define NUM_STATES 10000
#define BATCH      64
#define SEQLEN     4096
#define TPB        256
#define TPT        2                          // transitions per thread
#define BLOCKS_PER_SEQ (SEQLEN / (TPB * TPT)) // 8
#define GRID       (BATCH * BLOCKS_PER_SEQ)   // 512

// Scratch (device globals per harness rules)
__device__ float        g_partials[GRID];
__device__ unsigned int g_counter = 0;

__global__ __launch_bounds__(TPB)
void markov_fused_kernel(const int*   __restrict__ seqs,
                         const int*   __restrict__ lengths,
                         const float* __restrict__ initial,
                         const float* __restrict__ trans,
                         float*       __restrict__ out)
{
    const int b    = blockIdx.x >> 3;           // sequence id (8 blocks per sequence)
    const int blk  = blockIdx.x & 7;
    const int tid  = threadIdx.x;
    const int k    = blk * TPB + tid;           // 0..2047 within sequence
    const int base = 2 * k;                     // aligned prev-state base index
    const int len  = lengths[b];
    const int* s   = seqs + b * SEQLEN;

    // states s[base], s[base+1] via aligned int2; s[base+2] guarded (edge)
    const int2 pv = *reinterpret_cast<const int2*>(s + base);
    const int  p0 = pv.x;
    const int  p1 = pv.y;
    const int  p2 = (base + 2 < SEQLEN) ? s[base + 2] : 0;

    // Both gathers issued unconditionally, back-to-back (indices always in range).
    // Validity masking applied on the result only.
    const float pr0 = __ldg(&trans[(size_t)p0 * NUM_STATES + p1]);
    const float pr1 = __ldg(&trans[(size_t)p1 * NUM_STATES + p2]);

    // transition target indices: t0 = base+1 (always <= 4095), t1 = base+2.
    // t1 == 4096 only at the tail, where t1 < len is necessarily false (len <= 4096).
    const int t0 = base + 1;
    const int t1 = base + 2;
    float v = (t0 < len ? __logf(pr0) : 0.0f)
            + (t1 < len ? __logf(pr1) : 0.0f);

    // ---- block reduction (warp shuffle + shared) ----
    #pragma unroll
    for (int off = 16; off > 0; off >>= 1)
        v += __shfl_down_sync(0xffffffff, v, off);

    __shared__ float warp_sums[TPB / 32];
    const int lane = tid & 31;
    const int wid  = tid >> 5;
    if (lane == 0) warp_sums[wid] = v;
    __syncthreads();

    if (wid == 0) {
        v = (lane < TPB / 32) ? warp_sums[lane] : 0.0f;
        #pragma unroll
        for (int off = 4; off > 0; off >>= 1)
            v += __shfl_down_sync(0xffffffff, v, off);
        if (lane == 0)
            g_partials[blockIdx.x] = v;   // seq b's partials at [8b .. 8b+7]
    }

    // ---- last-block-done finalize (single launch, deterministic) ----
    __shared__ bool isLast;
    if (tid == 0) {
        __threadfence();
        const unsigned int done = atomicAdd(&g_counter, 1u);
        isLast = (done == GRID - 1);
    }
    __syncthreads();
    if (!isLast) return;

    float ll = 0.0f;
    if (tid < BATCH) {
        ll = __logf(__ldg(&initial[__ldg(&seqs[tid * SEQLEN])]));
        #pragma unroll
        for (int c = 0; c < BLOCKS_PER_SEQ; c++)
            ll += g_partials[tid * BLOCKS_PER_SEQ + c];
    }

    __shared__ float sll[BATCH];
    if (tid < BATCH) sll[tid] = ll;
    __syncthreads();

    if (tid == 0) {
        float m = -CUDART_INF_F;
        #pragma unroll 8
        for (int i = 0; i < BATCH; i++)
            m = fmaxf(m, sll[i]);
        float ssum = 0.0f;
        #pragma unroll 8
        for (int i = 0; i < BATCH; i++)
            ssum += __expf(sll[i] - m);
        out[0] = -(m + __logf(ssum));
        g_counter = 0;   // reset for next graph replay (determinism)
    }
}

extern "C" void kernel_launch(void* const* d_in, const int* in_sizes, int n_in,
                              void* d_out, int out_size)
{
    const int*   seqs    = (const int*)d_in[0];
    const int*   lengths = (const int*)d_in[1];
    const float* initial = (const float*)d_in[2];
    const float* trans   = (const float*)d_in[3];
    float*       out     = (float*)d_out;

    markov_fused_kernel<<<GRID, TPB>>>(seqs, lengths, initial, trans, out);
}